// round 16
// baseline (speedup 1.0000x reference)
#include <cuda_runtime.h>
#include <cuda_bf16.h>
#include <math.h>
#include <stdint.h>

// ---------------- problem constants ----------------
#define Bb      2
#define Ss      2048
#define HIDc    2048
#define NHh     16
#define DNOPE   128
#define DROPE   64
#define DVv     128
#define DQK     192
#define KVRANK  512
#define NTOK    (Bb*Ss)            // 4096
#define KVA_PAD 640
#define QSCALE (0.072168783648703220563f * 1.4426950408889634f)   // scale * log2(e)
#define LN_EPS 1e-5f

// ---------------- scratch (static device globals) ----------------
__device__ float g_kva  [(size_t)NTOK * KVA_PAD];
// bf16 split operands for GEMMs
__device__ __nv_bfloat16 g_hs_h [(size_t)NTOK * HIDc];
__device__ __nv_bfloat16 g_hs_l [(size_t)NTOK * HIDc];
__device__ __nv_bfloat16 g_WqT_h [(size_t)3072 * HIDc];
__device__ __nv_bfloat16 g_WqT_l [(size_t)3072 * HIDc];
__device__ __nv_bfloat16 g_WkvaT_h[(size_t)KVA_PAD * HIDc];
__device__ __nv_bfloat16 g_WkvaT_l[(size_t)KVA_PAD * HIDc];
__device__ __nv_bfloat16 g_WkvbT_h[(size_t)4096 * KVRANK];
__device__ __nv_bfloat16 g_WkvbT_l[(size_t)4096 * KVRANK];
__device__ __nv_bfloat16 g_WoT_h [(size_t)HIDc * HIDc];
__device__ __nv_bfloat16 g_WoT_l [(size_t)HIDc * HIDc];
__device__ __nv_bfloat16 g_kvlat_h[(size_t)NTOK * KVRANK];
__device__ __nv_bfloat16 g_kvlat_l[(size_t)NTOK * KVRANK];
__device__ __nv_bfloat16 g_attn_h[(size_t)NTOK * NHh * DVv];
__device__ __nv_bfloat16 g_attn_l[(size_t)NTOK * NHh * DVv];
// head-major attention operands [h][tok][d]
__device__ __nv_bfloat16 g_qh[(size_t)NHh * NTOK * DQK];
__device__ __nv_bfloat16 g_ql[(size_t)NHh * NTOK * DQK];
__device__ __nv_bfloat16 g_kh[(size_t)NHh * NTOK * DQK];
__device__ __nv_bfloat16 g_kl[(size_t)NHh * NTOK * DQK];
__device__ __nv_bfloat16 g_vh[(size_t)NHh * NTOK * DVv];
__device__ __nv_bfloat16 g_vl[(size_t)NHh * NTOK * DVv];

// ================= helpers =================
__device__ __forceinline__ uint32_t smem_u32(const void* p) {
    uint32_t a;
    asm("{ .reg .u64 t; cvta.to.shared.u64 t, %1; cvt.u32.u64 %0, t; }" : "=r"(a) : "l"(p));
    return a;
}
__device__ __forceinline__ void ldsm4(uint32_t* r, uint32_t addr) {
    asm volatile("ldmatrix.sync.aligned.m8n8.x4.shared.b16 {%0,%1,%2,%3}, [%4];"
        : "=r"(r[0]), "=r"(r[1]), "=r"(r[2]), "=r"(r[3]) : "r"(addr));
}
__device__ __forceinline__ void ldsm4t(uint32_t* r, uint32_t addr) {
    asm volatile("ldmatrix.sync.aligned.m8n8.x4.trans.shared.b16 {%0,%1,%2,%3}, [%4];"
        : "=r"(r[0]), "=r"(r[1]), "=r"(r[2]), "=r"(r[3]) : "r"(addr));
}
__device__ __forceinline__ void mma16816(float* d, const uint32_t* a, const uint32_t* b) {
    asm volatile("mma.sync.aligned.m16n8k16.row.col.f32.bf16.bf16.f32 "
        "{%0,%1,%2,%3}, {%4,%5,%6,%7}, {%8,%9}, {%0,%1,%2,%3};"
        : "+f"(d[0]), "+f"(d[1]), "+f"(d[2]), "+f"(d[3])
        : "r"(a[0]), "r"(a[1]), "r"(a[2]), "r"(a[3]), "r"(b[0]), "r"(b[1]));
}
__device__ __forceinline__ float ex2f(float x) {
    float y; asm("ex2.approx.f32 %0, %1;" : "=f"(y) : "f"(x)); return y;
}
__device__ __forceinline__ uint32_t pk2(__nv_bfloat16 a, __nv_bfloat16 b) {
    __nv_bfloat162 t(a, b); return *reinterpret_cast<uint32_t*>(&t);
}
__device__ __forceinline__ void split2(float v0, float v1, uint32_t& hw, uint32_t& lw) {
    __nv_bfloat16 h0 = __float2bfloat16(v0), h1 = __float2bfloat16(v1);
    hw = pk2(h0, h1);
    lw = pk2(__float2bfloat16(v0 - __bfloat162float(h0)),
             __float2bfloat16(v1 - __bfloat162float(h1)));
}

// ============ mma.sync bf16-split GEMM: C[M,N] = A[M,K] @ B^T[N,K] ============
// row0: global row offset of A block (for MODE 1/2 epilogue token indexing).
#define BKp     40
#define TILE_B  (128 * BKp * 2)
#define STAGE_B (4 * TILE_B)              // 40960
#define GS_SMEM (2 * STAGE_B)             // 81920 -> 2 CTAs/SM

template<int MODE>
__global__ __launch_bounds__(256, 2) void mma_gemm(
    const __nv_bfloat16* __restrict__ Ah, const __nv_bfloat16* __restrict__ Al,
    const __nv_bfloat16* __restrict__ Bh, const __nv_bfloat16* __restrict__ Bl,
    float* __restrict__ C, const float* __restrict__ fc, int row0, int M, int N, int K)
{
    extern __shared__ char dsm[];
    const uint32_t sbase = smem_u32(dsm);
    const int tid = threadIdx.x, wid = tid >> 5, lane = tid & 31;
    const int wm = wid >> 2, wn = wid & 3;
    const int bm = blockIdx.y * 128, bn = blockIdx.x * 128;

    const __nv_bfloat16* srcs[4] = {
        Ah + (size_t)bm * K, Al + (size_t)bm * K,
        Bh + (size_t)bn * K, Bl + (size_t)bn * K };

    auto load_chunk = [&](int c, int s) {
        #pragma unroll
        for (int t = 0; t < 4; t++) {
            const __nv_bfloat16* src = srcs[t] + c * 32;
            uint32_t tb = sbase + s * STAGE_B + t * TILE_B;
            #pragma unroll
            for (int i = 0; i < 2; i++) {
                int u = tid + i * 256;
                int row = u >> 2, c8 = u & 3;
                const void* g = src + (size_t)row * K + c8 * 8;
                uint32_t d = tb + (uint32_t)(row * BKp + c8 * 8) * 2;
                asm volatile("cp.async.cg.shared.global [%0], [%1], 16;" :: "r"(d), "l"(g));
            }
        }
        asm volatile("cp.async.commit_group;" ::: "memory");
    };

    float acc[16][4];
    #pragma unroll
    for (int i = 0; i < 16; i++)
        #pragma unroll
        for (int j = 0; j < 4; j++) acc[i][j] = 0.f;

    const int nchunk = K >> 5;
    load_chunk(0, 0);

    const uint32_t a_off = (uint32_t)((wm * 64 + (lane & 15)) * BKp + ((lane >> 4) << 3)) * 2;
    const uint32_t b_off = (uint32_t)((wn * 32 + (lane & 15)) * BKp + ((lane >> 4) << 3)) * 2;

    for (int c = 0; c < nchunk; c++) {
        const int s = c & 1;
        if (c + 1 < nchunk) {
            load_chunk(c + 1, s ^ 1);
            asm volatile("cp.async.wait_group 1;" ::: "memory");
        } else {
            asm volatile("cp.async.wait_group 0;" ::: "memory");
        }
        __syncthreads();
        const uint32_t stg = sbase + s * STAGE_B;
        #pragma unroll
        for (int ks = 0; ks < 2; ks++) {
            const uint32_t k0b = (uint32_t)(ks * 16) * 2;
            uint32_t ah4[4][4], al4[4][4], bhf[8], blf[8];
            #pragma unroll
            for (int mi = 0; mi < 4; mi++) {
                const uint32_t arow = a_off + (uint32_t)(mi * 16 * BKp) * 2 + k0b;
                ldsm4(ah4[mi], stg            + arow);
                ldsm4(al4[mi], stg + TILE_B   + arow);
            }
            #pragma unroll
            for (int ni = 0; ni < 2; ni++) {
                const uint32_t brow = b_off + (uint32_t)(ni * 16 * BKp) * 2 + k0b;
                ldsm4(&bhf[ni*4], stg + 2*TILE_B + brow);
                ldsm4(&blf[ni*4], stg + 3*TILE_B + brow);
            }
            #pragma unroll
            for (int mi = 0; mi < 4; mi++)
                #pragma unroll
                for (int nj = 0; nj < 4; nj++) {
                    uint32_t b2[2] = { bhf[(nj>>1)*4 + (nj&1)], bhf[(nj>>1)*4 + (nj&1) + 2] };
                    mma16816(acc[mi*4+nj], ah4[mi], b2);
                }
            #pragma unroll
            for (int mi = 0; mi < 4; mi++)
                #pragma unroll
                for (int nj = 0; nj < 4; nj++) {
                    uint32_t b2[2] = { blf[(nj>>1)*4 + (nj&1)], blf[(nj>>1)*4 + (nj&1) + 2] };
                    mma16816(acc[mi*4+nj], ah4[mi], b2);
                }
            #pragma unroll
            for (int mi = 0; mi < 4; mi++)
                #pragma unroll
                for (int nj = 0; nj < 4; nj++) {
                    uint32_t b2[2] = { bhf[(nj>>1)*4 + (nj&1)], bhf[(nj>>1)*4 + (nj&1) + 2] };
                    mma16816(acc[mi*4+nj], al4[mi], b2);
                }
        }
        __syncthreads();
    }

    // ---------------- epilogues ----------------
    #pragma unroll
    for (int mi = 0; mi < 4; mi++) {
        const int r0 = bm + wm * 64 + mi * 16 + (lane >> 2);
        #pragma unroll
        for (int nj = 0; nj < 4; nj++) {
            const int col = bn + wn * 32 + nj * 8 + (lane & 3) * 2;
            float* d = acc[mi * 4 + nj];
            if (MODE == 0) {
                *(float2*)&C[(size_t)r0 * N + col]       = make_float2(d[0], d[1]);
                *(float2*)&C[(size_t)(r0 + 8) * N + col] = make_float2(d[2], d[3]);
            } else if (MODE == 1) {
                const int h = col >> 8, dd = col & 255;
                #pragma unroll
                for (int rr = 0; rr < 2; rr++) {
                    const int tok = row0 + r0 + rr * 8;
                    uint32_t hw, lw;
                    split2(d[rr*2], d[rr*2+1], hw, lw);
                    if (dd < 128) {
                        size_t dst = ((size_t)h * NTOK + tok) * DQK + dd;
                        *(uint32_t*)&g_kh[dst] = hw;
                        *(uint32_t*)&g_kl[dst] = lw;
                    } else {
                        size_t dst = ((size_t)h * NTOK + tok) * DVv + (dd - 128);
                        *(uint32_t*)&g_vh[dst] = hw;
                        *(uint32_t*)&g_vl[dst] = lw;
                    }
                }
            } else {
                const int h = col / DQK, dd = col % DQK;
                #pragma unroll
                for (int rr = 0; rr < 2; rr++) {
                    const int tok = row0 + r0 + rr * 8;
                    float a0 = d[rr*2], a1 = d[rr*2+1], y0, y1;
                    if (dd < DNOPE) { y0 = a0 * QSCALE; y1 = a1 * QSCALE; }
                    else {
                        const int pi = (dd - DNOPE) >> 1;
                        float cc = fc[(size_t)(tok & (Ss-1)) * 64 + 2*pi];
                        float sn = fc[(size_t)(tok & (Ss-1)) * 64 + 2*pi + 1];
                        y0 = (a0 * cc - a1 * sn) * QSCALE;
                        y1 = (a0 * sn + a1 * cc) * QSCALE;
                    }
                    uint32_t hw, lw;
                    split2(y0, y1, hw, lw);
                    size_t dst = ((size_t)h * NTOK + tok) * DQK + dd;
                    *(uint32_t*)&g_qh[dst] = hw;
                    *(uint32_t*)&g_ql[dst] = lw;
                }
            }
        }
    }
}

// ---------------- split fp32 -> (hi, lo) bf16 ----------------
__global__ void split_rows_kernel(const float4* __restrict__ X,
                                  __nv_bfloat162* __restrict__ H,
                                  __nv_bfloat162* __restrict__ L, int n4)
{
    int i = blockIdx.x * blockDim.x + threadIdx.x;
    if (i >= n4) return;
    float4 v = X[i];
    uint32_t hw, lw;
    split2(v.x, v.y, hw, lw);
    *(uint32_t*)&H[2*i] = hw; *(uint32_t*)&L[2*i] = lw;
    split2(v.z, v.w, hw, lw);
    *(uint32_t*)&H[2*i+1] = hw; *(uint32_t*)&L[2*i+1] = lw;
}

__global__ void split_T_kernel(const float* __restrict__ W,
                               __nv_bfloat16* __restrict__ BTh,
                               __nv_bfloat16* __restrict__ BTl, int K, int N)
{
    __shared__ float t[32][33];
    const int k0 = blockIdx.y * 32, n0 = blockIdx.x * 32;
    const int tx = threadIdx.x, ty = threadIdx.y;
    #pragma unroll
    for (int i = 0; i < 32; i += 8) {
        int n = n0 + tx;
        t[ty + i][tx] = (n < N) ? W[(size_t)(k0 + ty + i) * N + n] : 0.f;
    }
    __syncthreads();
    #pragma unroll
    for (int i = 0; i < 32; i += 8) {
        int n = n0 + ty + i, k = k0 + tx;
        float v = t[tx][ty + i];
        __nv_bfloat16 hi = __float2bfloat16(v);
        BTh[(size_t)n * K + k] = hi;
        BTl[(size_t)n * K + k] = __float2bfloat16(v - __bfloat162float(hi));
    }
}

// ---------------- prep: LN(kv_lat) + k_rope -> all-head K split (per-batch) ----------------
__global__ __launch_bounds__(128) void prep_kernel(
    const float* __restrict__ fc, const float* __restrict__ lnw, const float* __restrict__ lnb,
    int tok0)
{
    const int tok = tok0 + blockIdx.x;
    const int s   = tok & (Ss - 1);
    const int tid = threadIdx.x;

    const float* x = &g_kva[(size_t)tok * KVA_PAD];
    float local[4];
    float sum = 0.f;
    #pragma unroll
    for (int i = 0; i < 4; i++) { local[i] = x[tid + i * 128]; sum += local[i]; }
    __shared__ float red[4];
    __shared__ float kr[64];
    #pragma unroll
    for (int o = 16; o > 0; o >>= 1) sum += __shfl_xor_sync(0xffffffffu, sum, o);
    if ((tid & 31) == 0) red[tid >> 5] = sum;
    __syncthreads();
    const float mean = (red[0] + red[1] + red[2] + red[3]) * (1.f / 512.f);
    float vs = 0.f;
    #pragma unroll
    for (int i = 0; i < 4; i++) { float d = local[i] - mean; vs = fmaf(d, d, vs); }
    #pragma unroll
    for (int o = 16; o > 0; o >>= 1) vs += __shfl_xor_sync(0xffffffffu, vs, o);
    __syncthreads();
    if ((tid & 31) == 0) red[tid >> 5] = vs;
    if (tid < 32) {
        const float* fcs = &fc[(size_t)s * 64];
        float c  = fcs[tid * 2 + 0];
        float sn = fcs[tid * 2 + 1];
        float x0 = x[KVRANK + 2 * tid];
        float x1 = x[KVRANK + 2 * tid + 1];
        kr[2 * tid]     = x0 * c - x1 * sn;
        kr[2 * tid + 1] = x0 * sn + x1 * c;
    }
    __syncthreads();
    const float var  = (red[0] + red[1] + red[2] + red[3]) * (1.f / 512.f);
    const float rstd = rsqrtf(var + LN_EPS);
    #pragma unroll
    for (int i = 0; i < 4; i++) {
        int c = tid + i * 128;
        float v = (local[i] - mean) * rstd * lnw[c] + lnb[c];
        __nv_bfloat16 hi = __float2bfloat16(v);
        g_kvlat_h[(size_t)tok * KVRANK + c] = hi;
        g_kvlat_l[(size_t)tok * KVRANK + c] = __float2bfloat16(v - __bfloat162float(hi));
    }
    #pragma unroll
    for (int i = 0; i < 8; i++) {
        int e = tid + i * 128;
        int hh = e >> 6, k = e & 63;
        float v = kr[k];
        __nv_bfloat16 hi = __float2bfloat16(v);
        size_t dst = ((size_t)hh * NTOK + tok) * DQK + DNOPE + k;
        g_kh[dst] = hi;
        g_kl[dst] = __float2bfloat16(v - __bfloat162float(hi));
    }
}

// ---------------- flash attention v2: FQT=64, 128 threads, 2 CTAs/SM ----------------
#define FQT 64
#define FKT 32
#define QKB 400
#define VB  272
#define OQH 0
#define OKH 25600
#define OKL 51200
#define OVH 76800
#define OVL 94208
#define KSTG 12800
#define VSTG 8704
#define FSMEM 111616

__global__ __launch_bounds__(128) void flash_mma(int b)
{
    const int qt   = (int)gridDim.x - 1 - (int)blockIdx.x;
    const int h    = blockIdx.y;
    const int tid  = threadIdx.x, w = tid >> 5, lane = tid & 31;
    extern __shared__ char fsm[];
    const uint32_t sb = smem_u32(fsm);
    const int q0 = qt * FQT;
    const size_t rowQ = (size_t)h * NTOK + (size_t)b * Ss + q0;
    const size_t rowK = (size_t)h * NTOK + (size_t)b * Ss;

    #pragma unroll
    for (int i = 0; i < 12; i++) {
        int u = tid + i * 128;
        int row = u / 24, c = u % 24;
        const void* src = g_qh + (rowQ + row) * DQK + c * 8;
        uint32_t dst = sb + OQH + row * QKB + c * 16;
        asm volatile("cp.async.cg.shared.global [%0], [%1], 16;" :: "r"(dst), "l"(src));
    }
    #pragma unroll
    for (int i = 0; i < 12; i++) {
        int u = tid + i * 128;
        int row = u / 24, c = u % 24;
        const void* src = g_ql + (rowQ + row) * DQK + c * 8;
        uint32_t dst = sb + OVH + row * QKB + c * 16;
        asm volatile("cp.async.cg.shared.global [%0], [%1], 16;" :: "r"(dst), "l"(src));
    }
    asm volatile("cp.async.commit_group;" ::: "memory");
    asm volatile("cp.async.wait_group 0;" ::: "memory");
    __syncthreads();

    uint32_t ql[12][4];
    {
        const uint32_t qlo_off = sb + OVH + (w * 16 + (lane & 15)) * QKB + ((lane >> 4) << 4);
        #pragma unroll
        for (int ks = 0; ks < 12; ks++) ldsm4(ql[ks], qlo_off + ks * 32);
    }
    __syncthreads();

    auto load_kv = [&](int j, int st) {
        const int j0 = j * FKT;
        #pragma unroll
        for (int i = 0; i < 12; i++) {
            int u = tid + i * 128;
            int sp = (u >= 768); int uu = u - sp * 768;
            int row = uu / 24, c = uu % 24;
            const void* src = (sp ? g_kl : g_kh) + (rowK + j0 + row) * DQK + c * 8;
            uint32_t dst = sb + (sp ? OKL : OKH) + st * KSTG + row * QKB + c * 16;
            asm volatile("cp.async.cg.shared.global [%0], [%1], 16;" :: "r"(dst), "l"(src));
        }
        #pragma unroll
        for (int i = 0; i < 8; i++) {
            int u = tid + i * 128;
            int sp = (u >= 512); int uu = u - sp * 512;
            int row = uu >> 4, c = uu & 15;
            const void* src = (sp ? g_vl : g_vh) + (rowK + j0 + row) * DVv + c * 8;
            uint32_t dst = sb + (sp ? OVL : OVH) + st * VSTG + row * VB + c * 16;
            asm volatile("cp.async.cg.shared.global [%0], [%1], 16;" :: "r"(dst), "l"(src));
        }
        asm volatile("cp.async.commit_group;" ::: "memory");
    };
    load_kv(0, 0);

    float o[16][4];
    #pragma unroll
    for (int t = 0; t < 16; t++)
        #pragma unroll
        for (int e = 0; e < 4; e++) o[t][e] = 0.f;
    float mr[2] = {-1e30f, -1e30f}, lr[2] = {0.f, 0.f};

    const uint32_t q_off = sb + OQH + (w * 16 + (lane & 15)) * QKB + ((lane >> 4) << 4);
    const uint32_t kz = (lane & 15) * QKB + ((lane >> 4) << 4);
    const uint32_t vz = (lane & 15) * VB  + ((lane >> 4) << 4);
    const int nkt = q0 / FKT + 2;

    for (int j = 0; j < nkt; j++) {
        const int st = j & 1, j0 = j * FKT;
        if (j + 1 < nkt) {
            load_kv(j + 1, st ^ 1);
            asm volatile("cp.async.wait_group 1;" ::: "memory");
        } else {
            asm volatile("cp.async.wait_group 0;" ::: "memory");
        }
        __syncthreads();

        float sacc[4][4];
        #pragma unroll
        for (int t = 0; t < 4; t++)
            #pragma unroll
            for (int e = 0; e < 4; e++) sacc[t][e] = 0.f;

        #pragma unroll
        for (int ks = 0; ks < 12; ks++) {
            uint32_t qh4[4];
            ldsm4(qh4, q_off + ks * 32);
            #pragma unroll
            for (int nw = 0; nw < 2; nw++) {
                uint32_t kh4[4], kl4[4];
                uint32_t ka = sb + OKH + st * KSTG + nw * 16 * QKB + kz + ks * 32;
                ldsm4(kh4, ka);
                ldsm4(kl4, ka + (OKL - OKH));
                uint32_t bh0[2] = {kh4[0], kh4[2]}, bh1[2] = {kh4[1], kh4[3]};
                uint32_t bl0[2] = {kl4[0], kl4[2]}, bl1[2] = {kl4[1], kl4[3]};
                mma16816(sacc[nw * 2],     qh4,    bh0);
                mma16816(sacc[nw * 2 + 1], qh4,    bh1);
                mma16816(sacc[nw * 2],     qh4,    bl0);
                mma16816(sacc[nw * 2 + 1], qh4,    bl1);
                mma16816(sacc[nw * 2],     ql[ks], bh0);
                mma16816(sacc[nw * 2 + 1], ql[ks], bh1);
            }
        }

        if (j0 + FKT - 1 > q0) {
            #pragma unroll
            for (int t = 0; t < 4; t++)
                #pragma unroll
                for (int e = 0; e < 4; e++) {
                    int rowg = q0 + w * 16 + (lane >> 2) + (e >> 1) * 8;
                    int colg = j0 + t * 8 + (lane & 3) * 2 + (e & 1);
                    if (colg > rowg) sacc[t][e] = -1e30f;
                }
        }

        float alpha[2];
        #pragma unroll
        for (int rh = 0; rh < 2; rh++) {
            float mx = -1e30f;
            #pragma unroll
            for (int t = 0; t < 4; t++)
                mx = fmaxf(mx, fmaxf(sacc[t][rh * 2], sacc[t][rh * 2 + 1]));
            mx = fmaxf(mx, __shfl_xor_sync(0xffffffffu, mx, 1));
            mx = fmaxf(mx, __shfl_xor_sync(0xffffffffu, mx, 2));
            float mn = fmaxf(mr[rh], mx);
            alpha[rh] = ex2f(mr[rh] - mn);
            mr[rh] = mn;
            float rs = 0.f;
            #pragma unroll
            for (int t = 0; t < 4; t++) {
                float p0 = ex2f(sacc[t][rh * 2]     - mn);
                float p1 = ex2f(sacc[t][rh * 2 + 1] - mn);
                sacc[t][rh * 2] = p0; sacc[t][rh * 2 + 1] = p1;
                rs += p0 + p1;
            }
            rs += __shfl_xor_sync(0xffffffffu, rs, 1);
            rs += __shfl_xor_sync(0xffffffffu, rs, 2);
            lr[rh] = lr[rh] * alpha[rh] + rs;
        }
        #pragma unroll
        for (int t = 0; t < 16; t++) {
            o[t][0] *= alpha[0]; o[t][1] *= alpha[0];
            o[t][2] *= alpha[1]; o[t][3] *= alpha[1];
        }

        uint32_t ah[2][4], al[2][4];
        #pragma unroll
        for (int ks2 = 0; ks2 < 2; ks2++) {
            #pragma unroll
            for (int q = 0; q < 4; q++) {
                int t = ks2 * 2 + (q >> 1);
                int e = (q & 1) * 2;
                split2(sacc[t][e], sacc[t][e + 1], ah[ks2][q], al[ks2][q]);
            }
        }

        #pragma unroll
        for (int ks2 = 0; ks2 < 2; ks2++) {
            #pragma unroll
            for (int nw = 0; nw < 8; nw++) {
                uint32_t vh4[4], vl4[4];
                uint32_t va = sb + OVH + st * VSTG + ks2 * 16 * VB + vz + nw * 32;
                ldsm4t(vh4, va);
                ldsm4t(vl4, va + (OVL - OVH));
                uint32_t b0h[2] = {vh4[0], vh4[1]}, b1h[2] = {vh4[2], vh4[3]};
                uint32_t b0l[2] = {vl4[0], vl4[1]}, b1l[2] = {vl4[2], vl4[3]};
                mma16816(o[nw * 2],     ah[ks2], b0h);
                mma16816(o[nw * 2 + 1], ah[ks2], b1h);
                mma16816(o[nw * 2],     al[ks2], b0h);
                mma16816(o[nw * 2 + 1], al[ks2], b1h);
                mma16816(o[nw * 2],     ah[ks2], b0l);
                mma16816(o[nw * 2 + 1], ah[ks2], b1l);
            }
        }
        __syncthreads();
    }

    #pragma unroll
    for (int rh = 0; rh < 2; rh++) {
        float inv = 1.f / lr[rh];
        int row = q0 + w * 16 + (lane >> 2) + rh * 8;
        size_t gbase = ((size_t)b * Ss + row) * (NHh * DVv) + h * DVv;
        #pragma unroll
        for (int t = 0; t < 16; t++) {
            int d = t * 8 + (lane & 3) * 2;
            uint32_t hw, lw;
            split2(o[t][rh * 2] * inv, o[t][rh * 2 + 1] * inv, hw, lw);
            *(uint32_t*)&g_attn_h[gbase + d] = hw;
            *(uint32_t*)&g_attn_l[gbase + d] = lw;
        }
    }
}

// ---------------- launch: per-batch pipelining; every record precedes its waits ----------------
extern "C" void kernel_launch(void* const* d_in, const int* in_sizes, int n_in,
                              void* d_out, int out_size)
{
    const float* hs   = (const float*)d_in[0];
    const float* fc   = (const float*)d_in[1];
    const float* Wq   = (const float*)d_in[3];
    const float* Wkva = (const float*)d_in[4];
    const float* lnw  = (const float*)d_in[5];
    const float* lnb  = (const float*)d_in[6];
    const float* Wkvb = (const float*)d_in[7];
    const float* Wo   = (const float*)d_in[8];
    float* out = (float*)d_out;

    static bool init_done = false;
    static float *p_kva;
    static __nv_bfloat16 *p_hs_h, *p_hs_l, *p_WqT_h, *p_WqT_l, *p_WkvaT_h, *p_WkvaT_l,
                         *p_WkvbT_h, *p_WkvbT_l, *p_WoT_h, *p_WoT_l,
                         *p_kvlat_h, *p_kvlat_l, *p_attn_h, *p_attn_l;
    static cudaStream_t sA, sB;
    static cudaEvent_t evRoot, evWA, evWB, evWo, evA2, evB2;
    if (!init_done) {
        cudaGetSymbolAddress((void**)&p_kva,    g_kva);
        cudaGetSymbolAddress((void**)&p_hs_h,   g_hs_h);
        cudaGetSymbolAddress((void**)&p_hs_l,   g_hs_l);
        cudaGetSymbolAddress((void**)&p_WqT_h,  g_WqT_h);
        cudaGetSymbolAddress((void**)&p_WqT_l,  g_WqT_l);
        cudaGetSymbolAddress((void**)&p_WkvaT_h,g_WkvaT_h);
        cudaGetSymbolAddress((void**)&p_WkvaT_l,g_WkvaT_l);
        cudaGetSymbolAddress((void**)&p_WkvbT_h,g_WkvbT_h);
        cudaGetSymbolAddress((void**)&p_WkvbT_l,g_WkvbT_l);
        cudaGetSymbolAddress((void**)&p_WoT_h,  g_WoT_h);
        cudaGetSymbolAddress((void**)&p_WoT_l,  g_WoT_l);
        cudaGetSymbolAddress((void**)&p_kvlat_h,g_kvlat_h);
        cudaGetSymbolAddress((void**)&p_kvlat_l,g_kvlat_l);
        cudaGetSymbolAddress((void**)&p_attn_h, g_attn_h);
        cudaGetSymbolAddress((void**)&p_attn_l, g_attn_l);
        cudaFuncSetAttribute(mma_gemm<0>,
                             cudaFuncAttributeMaxDynamicSharedMemorySize, GS_SMEM);
        cudaFuncSetAttribute(mma_gemm<1>,
                             cudaFuncAttributeMaxDynamicSharedMemorySize, GS_SMEM);
        cudaFuncSetAttribute(mma_gemm<2>,
                             cudaFuncAttributeMaxDynamicSharedMemorySize, GS_SMEM);
        cudaFuncSetAttribute(flash_mma,
                             cudaFuncAttributeMaxDynamicSharedMemorySize, FSMEM);
        cudaStreamCreateWithFlags(&sA, cudaStreamNonBlocking);
        cudaStreamCreateWithFlags(&sB, cudaStreamNonBlocking);
        cudaEventCreateWithFlags(&evRoot, cudaEventDisableTiming);
        cudaEventCreateWithFlags(&evWA,   cudaEventDisableTiming);
        cudaEventCreateWithFlags(&evWB,   cudaEventDisableTiming);
        cudaEventCreateWithFlags(&evWo,   cudaEventDisableTiming);
        cudaEventCreateWithFlags(&evA2,   cudaEventDisableTiming);
        cudaEventCreateWithFlags(&evB2,   cudaEventDisableTiming);
        init_done = true;
    }

    const size_t HB = (size_t)Ss * HIDc;       // per-batch hs elements
    const size_t QB = (size_t)Ss * KVRANK;     // per-batch kvlat elements

    // ---- root on origin stream, then fork ----
    {
        int n4 = NTOK * HIDc / 4;
        split_rows_kernel<<<(n4 + 255) / 256, 256>>>(
            (const float4*)hs, (__nv_bfloat162*)p_hs_h, (__nv_bfloat162*)p_hs_l, n4);
    }
    cudaEventRecord(evRoot, 0);
    cudaStreamWaitEvent(sA, evRoot, 0);
    cudaStreamWaitEvent(sB, evRoot, 0);

    // ---- sB part 1: kv weight splits (record BEFORE sA waits on it) ----
    split_T_kernel<<<dim3(KVA_PAD/32, HIDc/32), dim3(32,8), 0, sB>>>(Wkva, p_WkvaT_h, p_WkvaT_l, HIDc, 576);
    split_T_kernel<<<dim3(4096/32, KVRANK/32),  dim3(32,8), 0, sB>>>(Wkvb, p_WkvbT_h, p_WkvbT_l, KVRANK, 4096);
    cudaEventRecord(evWB, sB);

    // ---- sA: Wq split, batch 0 end-to-end ----
    split_T_kernel<<<dim3(3072/32, HIDc/32), dim3(32,8), 0, sA>>>(Wq, p_WqT_h, p_WqT_l, HIDc, 3072);
    cudaEventRecord(evWA, sA);
    mma_gemm<2><<<dim3(3072/128, Ss/128), 256, GS_SMEM, sA>>>(
        p_hs_h, p_hs_l, p_WqT_h, p_WqT_l, nullptr, fc, 0, Ss, 3072, HIDc);
    split_T_kernel<<<dim3(2048/32, HIDc/32), dim3(32,8), 0, sA>>>(Wo, p_WoT_h, p_WoT_l, HIDc, 2048);
    cudaEventRecord(evWo, sA);
    cudaStreamWaitEvent(sA, evWB, 0);             // evWB recorded above ✓
    mma_gemm<0><<<dim3(KVA_PAD/128, Ss/128), 256, GS_SMEM, sA>>>(
        p_hs_h, p_hs_l, p_WkvaT_h, p_WkvaT_l, p_kva, nullptr, 0, Ss, KVA_PAD, HIDc);
    prep_kernel<<<Ss, 128, 0, sA>>>(fc, lnw, lnb, 0);
    mma_gemm<1><<<dim3(4096/128, Ss/128), 256, GS_SMEM, sA>>>(
        p_kvlat_h, p_kvlat_l, p_WkvbT_h, p_WkvbT_l, nullptr, nullptr, 0, Ss, 4096, KVRANK);
    flash_mma<<<dim3(Ss/FQT, NHh), 128, FSMEM, sA>>>(0);
    mma_gemm<0><<<dim3(2048/128, Ss/128), 256, GS_SMEM, sA>>>(
        p_attn_h, p_attn_l, p_WoT_h, p_WoT_l, out, nullptr, 0, Ss, 2048, HIDc);

    // ---- sB part 2: batch 1 end-to-end ----
    cudaStreamWaitEvent(sB, evWA, 0);             // evWA recorded above ✓
    mma_gemm<2><<<dim3(3072/128, Ss/128), 256, GS_SMEM, sB>>>(
        p_hs_h + HB, p_hs_l + HB, p_WqT_h, p_WqT_l, nullptr, fc, Ss, Ss, 3072, HIDc);
    mma_gemm<0><<<dim3(KVA_PAD/128, Ss/128), 256, GS_SMEM, sB>>>(
        p_hs_h + HB, p_hs_l + HB, p_WkvaT_h, p_WkvaT_l, p_kva + (size_t)Ss * KVA_PAD,
        nullptr, 0, Ss, KVA_PAD, HIDc);
    prep_kernel<<<Ss, 128, 0, sB>>>(fc, lnw, lnb, Ss);
    mma_gemm<1><<<dim3(4096/128, Ss/128), 256, GS_SMEM, sB>>>(
        p_kvlat_h + QB, p_kvlat_l + QB, p_WkvbT_h, p_WkvbT_l, nullptr, nullptr, Ss, Ss, 4096, KVRANK);
    flash_mma<<<dim3(Ss/FQT, NHh), 128, FSMEM, sB>>>(1);
    cudaStreamWaitEvent(sB, evWo, 0);             // evWo recorded above ✓
    mma_gemm<0><<<dim3(2048/128, Ss/128), 256, GS_SMEM, sB>>>(
        p_attn_h + (size_t)Ss * HIDc, p_attn_l + (size_t)Ss * HIDc,
        p_WoT_h, p_WoT_l, out + (size_t)Ss * HIDc, nullptr, 0, Ss, 2048, HIDc);

    // ---- join back to origin stream ----
    cudaEventRecord(evA2, sA);
    cudaEventRecord(evB2, sB);
    cudaStreamWaitEvent(0, evA2, 0);
    cudaStreamWaitEvent(0, evB2, 0);
}

// round 17
// speedup vs baseline: 1.0042x; 1.0042x over previous
#include <cuda_runtime.h>
#include <cuda_bf16.h>
#include <math.h>
#include <stdint.h>

// ---------------- problem constants ----------------
#define Bb      2
#define Ss      2048
#define HIDc    2048
#define NHh     16
#define DNOPE   128
#define DROPE   64
#define DVv     128
#define DQK     192
#define KVRANK  512
#define NTOK    (Bb*Ss)            // 4096
#define KVA_PAD 640
#define QSCALE (0.072168783648703220563f * 1.4426950408889634f)   // scale * log2(e)
#define LN_EPS 1e-5f

// ---------------- scratch (static device globals) ----------------
__device__ float g_kva  [(size_t)NTOK * KVA_PAD];
// bf16 split operands for GEMMs
__device__ __nv_bfloat16 g_hs_h [(size_t)NTOK * HIDc];
__device__ __nv_bfloat16 g_hs_l [(size_t)NTOK * HIDc];
__device__ __nv_bfloat16 g_WqT_h [(size_t)3072 * HIDc];
__device__ __nv_bfloat16 g_WqT_l [(size_t)3072 * HIDc];
__device__ __nv_bfloat16 g_WkvaT_h[(size_t)KVA_PAD * HIDc];
__device__ __nv_bfloat16 g_WkvaT_l[(size_t)KVA_PAD * HIDc];
__device__ __nv_bfloat16 g_WkvbT_h[(size_t)4096 * KVRANK];
__device__ __nv_bfloat16 g_WkvbT_l[(size_t)4096 * KVRANK];
__device__ __nv_bfloat16 g_WoT_h [(size_t)HIDc * HIDc];
__device__ __nv_bfloat16 g_WoT_l [(size_t)HIDc * HIDc];
__device__ __nv_bfloat16 g_kvlat_h[(size_t)NTOK * KVRANK];
__device__ __nv_bfloat16 g_kvlat_l[(size_t)NTOK * KVRANK];
__device__ __nv_bfloat16 g_attn_h[(size_t)NTOK * NHh * DVv];
__device__ __nv_bfloat16 g_attn_l[(size_t)NTOK * NHh * DVv];
// head-major attention operands [h][tok][d]
__device__ __nv_bfloat16 g_qh[(size_t)NHh * NTOK * DQK];
__device__ __nv_bfloat16 g_ql[(size_t)NHh * NTOK * DQK];
__device__ __nv_bfloat16 g_kh[(size_t)NHh * NTOK * DQK];
__device__ __nv_bfloat16 g_kl[(size_t)NHh * NTOK * DQK];
__device__ __nv_bfloat16 g_vh[(size_t)NHh * NTOK * DVv];
__device__ __nv_bfloat16 g_vl[(size_t)NHh * NTOK * DVv];

// ================= helpers =================
__device__ __forceinline__ uint32_t smem_u32(const void* p) {
    uint32_t a;
    asm("{ .reg .u64 t; cvta.to.shared.u64 t, %1; cvt.u32.u64 %0, t; }" : "=r"(a) : "l"(p));
    return a;
}
__device__ __forceinline__ void ldsm4(uint32_t* r, uint32_t addr) {
    asm volatile("ldmatrix.sync.aligned.m8n8.x4.shared.b16 {%0,%1,%2,%3}, [%4];"
        : "=r"(r[0]), "=r"(r[1]), "=r"(r[2]), "=r"(r[3]) : "r"(addr));
}
__device__ __forceinline__ void ldsm4t(uint32_t* r, uint32_t addr) {
    asm volatile("ldmatrix.sync.aligned.m8n8.x4.trans.shared.b16 {%0,%1,%2,%3}, [%4];"
        : "=r"(r[0]), "=r"(r[1]), "=r"(r[2]), "=r"(r[3]) : "r"(addr));
}
__device__ __forceinline__ void mma16816(float* d, const uint32_t* a, const uint32_t* b) {
    asm volatile("mma.sync.aligned.m16n8k16.row.col.f32.bf16.bf16.f32 "
        "{%0,%1,%2,%3}, {%4,%5,%6,%7}, {%8,%9}, {%0,%1,%2,%3};"
        : "+f"(d[0]), "+f"(d[1]), "+f"(d[2]), "+f"(d[3])
        : "r"(a[0]), "r"(a[1]), "r"(a[2]), "r"(a[3]), "r"(b[0]), "r"(b[1]));
}
__device__ __forceinline__ float ex2f(float x) {
    float y; asm("ex2.approx.f32 %0, %1;" : "=f"(y) : "f"(x)); return y;
}
__device__ __forceinline__ uint32_t pk2(__nv_bfloat16 a, __nv_bfloat16 b) {
    __nv_bfloat162 t(a, b); return *reinterpret_cast<uint32_t*>(&t);
}
__device__ __forceinline__ void split2(float v0, float v1, uint32_t& hw, uint32_t& lw) {
    __nv_bfloat16 h0 = __float2bfloat16(v0), h1 = __float2bfloat16(v1);
    hw = pk2(h0, h1);
    lw = pk2(__float2bfloat16(v0 - __bfloat162float(h0)),
             __float2bfloat16(v1 - __bfloat162float(h1)));
}

// ============ mma.sync bf16-split GEMM: C[M,N] = A[M,K] @ B^T[N,K] ============
#define BKp     40
#define TILE_B  (128 * BKp * 2)
#define STAGE_B (4 * TILE_B)              // 40960
#define GS_SMEM (2 * STAGE_B)             // 81920 -> 2 CTAs/SM

template<int MODE>
__global__ __launch_bounds__(256, 2) void mma_gemm(
    const __nv_bfloat16* __restrict__ Ah, const __nv_bfloat16* __restrict__ Al,
    const __nv_bfloat16* __restrict__ Bh, const __nv_bfloat16* __restrict__ Bl,
    float* __restrict__ C, const float* __restrict__ fc, int M, int N, int K)
{
    extern __shared__ char dsm[];
    const uint32_t sbase = smem_u32(dsm);
    const int tid = threadIdx.x, wid = tid >> 5, lane = tid & 31;
    const int wm = wid >> 2, wn = wid & 3;
    const int bm = blockIdx.y * 128, bn = blockIdx.x * 128;

    const __nv_bfloat16* srcs[4] = {
        Ah + (size_t)bm * K, Al + (size_t)bm * K,
        Bh + (size_t)bn * K, Bl + (size_t)bn * K };

    auto load_chunk = [&](int c, int s) {
        #pragma unroll
        for (int t = 0; t < 4; t++) {
            const __nv_bfloat16* src = srcs[t] + c * 32;
            uint32_t tb = sbase + s * STAGE_B + t * TILE_B;
            #pragma unroll
            for (int i = 0; i < 2; i++) {
                int u = tid + i * 256;
                int row = u >> 2, c8 = u & 3;
                const void* g = src + (size_t)row * K + c8 * 8;
                uint32_t d = tb + (uint32_t)(row * BKp + c8 * 8) * 2;
                asm volatile("cp.async.cg.shared.global [%0], [%1], 16;" :: "r"(d), "l"(g));
            }
        }
        asm volatile("cp.async.commit_group;" ::: "memory");
    };

    float acc[16][4];
    #pragma unroll
    for (int i = 0; i < 16; i++)
        #pragma unroll
        for (int j = 0; j < 4; j++) acc[i][j] = 0.f;

    const int nchunk = K >> 5;
    load_chunk(0, 0);

    const uint32_t a_off = (uint32_t)((wm * 64 + (lane & 15)) * BKp + ((lane >> 4) << 3)) * 2;
    const uint32_t b_off = (uint32_t)((wn * 32 + (lane & 15)) * BKp + ((lane >> 4) << 3)) * 2;

    for (int c = 0; c < nchunk; c++) {
        const int s = c & 1;
        if (c + 1 < nchunk) {
            load_chunk(c + 1, s ^ 1);
            asm volatile("cp.async.wait_group 1;" ::: "memory");
        } else {
            asm volatile("cp.async.wait_group 0;" ::: "memory");
        }
        __syncthreads();
        const uint32_t stg = sbase + s * STAGE_B;
        #pragma unroll
        for (int ks = 0; ks < 2; ks++) {
            const uint32_t k0b = (uint32_t)(ks * 16) * 2;
            uint32_t ah4[4][4], al4[4][4], bhf[8], blf[8];
            #pragma unroll
            for (int mi = 0; mi < 4; mi++) {
                const uint32_t arow = a_off + (uint32_t)(mi * 16 * BKp) * 2 + k0b;
                ldsm4(ah4[mi], stg            + arow);
                ldsm4(al4[mi], stg + TILE_B   + arow);
            }
            #pragma unroll
            for (int ni = 0; ni < 2; ni++) {
                const uint32_t brow = b_off + (uint32_t)(ni * 16 * BKp) * 2 + k0b;
                ldsm4(&bhf[ni*4], stg + 2*TILE_B + brow);
                ldsm4(&blf[ni*4], stg + 3*TILE_B + brow);
            }
            #pragma unroll
            for (int mi = 0; mi < 4; mi++)
                #pragma unroll
                for (int nj = 0; nj < 4; nj++) {
                    uint32_t b2[2] = { bhf[(nj>>1)*4 + (nj&1)], bhf[(nj>>1)*4 + (nj&1) + 2] };
                    mma16816(acc[mi*4+nj], ah4[mi], b2);
                }
            #pragma unroll
            for (int mi = 0; mi < 4; mi++)
                #pragma unroll
                for (int nj = 0; nj < 4; nj++) {
                    uint32_t b2[2] = { blf[(nj>>1)*4 + (nj&1)], blf[(nj>>1)*4 + (nj&1) + 2] };
                    mma16816(acc[mi*4+nj], ah4[mi], b2);
                }
            #pragma unroll
            for (int mi = 0; mi < 4; mi++)
                #pragma unroll
                for (int nj = 0; nj < 4; nj++) {
                    uint32_t b2[2] = { bhf[(nj>>1)*4 + (nj&1)], bhf[(nj>>1)*4 + (nj&1) + 2] };
                    mma16816(acc[mi*4+nj], al4[mi], b2);
                }
        }
        __syncthreads();
    }

    // ---------------- epilogues ----------------
    #pragma unroll
    for (int mi = 0; mi < 4; mi++) {
        const int r0 = bm + wm * 64 + mi * 16 + (lane >> 2);
        #pragma unroll
        for (int nj = 0; nj < 4; nj++) {
            const int col = bn + wn * 32 + nj * 8 + (lane & 3) * 2;
            float* d = acc[mi * 4 + nj];
            if (MODE == 0) {
                *(float2*)&C[(size_t)r0 * N + col]       = make_float2(d[0], d[1]);
                *(float2*)&C[(size_t)(r0 + 8) * N + col] = make_float2(d[2], d[3]);
            } else if (MODE == 1) {
                const int h = col >> 8, dd = col & 255;
                #pragma unroll
                for (int rr = 0; rr < 2; rr++) {
                    const int tok = r0 + rr * 8;
                    uint32_t hw, lw;
                    split2(d[rr*2], d[rr*2+1], hw, lw);
                    if (dd < 128) {
                        size_t dst = ((size_t)h * NTOK + tok) * DQK + dd;
                        *(uint32_t*)&g_kh[dst] = hw;
                        *(uint32_t*)&g_kl[dst] = lw;
                    } else {
                        size_t dst = ((size_t)h * NTOK + tok) * DVv + (dd - 128);
                        *(uint32_t*)&g_vh[dst] = hw;
                        *(uint32_t*)&g_vl[dst] = lw;
                    }
                }
            } else {
                const int h = col / DQK, dd = col % DQK;
                #pragma unroll
                for (int rr = 0; rr < 2; rr++) {
                    const int tok = r0 + rr * 8;
                    float a0 = d[rr*2], a1 = d[rr*2+1], y0, y1;
                    if (dd < DNOPE) { y0 = a0 * QSCALE; y1 = a1 * QSCALE; }
                    else {
                        const int pi = (dd - DNOPE) >> 1;
                        float cc = fc[(size_t)(tok & (Ss-1)) * 64 + 2*pi];
                        float sn = fc[(size_t)(tok & (Ss-1)) * 64 + 2*pi + 1];
                        y0 = (a0 * cc - a1 * sn) * QSCALE;
                        y1 = (a0 * sn + a1 * cc) * QSCALE;
                    }
                    uint32_t hw, lw;
                    split2(y0, y1, hw, lw);
                    size_t dst = ((size_t)h * NTOK + tok) * DQK + dd;
                    *(uint32_t*)&g_qh[dst] = hw;
                    *(uint32_t*)&g_ql[dst] = lw;
                }
            }
        }
    }
}

// ---------------- split fp32 -> (hi, lo) bf16 ----------------
__global__ void split_rows_kernel(const float4* __restrict__ X,
                                  __nv_bfloat162* __restrict__ H,
                                  __nv_bfloat162* __restrict__ L, int n4)
{
    int i = blockIdx.x * blockDim.x + threadIdx.x;
    if (i >= n4) return;
    float4 v = X[i];
    uint32_t hw, lw;
    split2(v.x, v.y, hw, lw);
    *(uint32_t*)&H[2*i] = hw; *(uint32_t*)&L[2*i] = lw;
    split2(v.z, v.w, hw, lw);
    *(uint32_t*)&H[2*i+1] = hw; *(uint32_t*)&L[2*i+1] = lw;
}

__global__ void split_T_kernel(const float* __restrict__ W,
                               __nv_bfloat16* __restrict__ BTh,
                               __nv_bfloat16* __restrict__ BTl, int K, int N)
{
    __shared__ float t[32][33];
    const int k0 = blockIdx.y * 32, n0 = blockIdx.x * 32;
    const int tx = threadIdx.x, ty = threadIdx.y;
    #pragma unroll
    for (int i = 0; i < 32; i += 8) {
        int n = n0 + tx;
        t[ty + i][tx] = (n < N) ? W[(size_t)(k0 + ty + i) * N + n] : 0.f;
    }
    __syncthreads();
    #pragma unroll
    for (int i = 0; i < 32; i += 8) {
        int n = n0 + ty + i, k = k0 + tx;
        float v = t[tx][ty + i];
        __nv_bfloat16 hi = __float2bfloat16(v);
        BTh[(size_t)n * K + k] = hi;
        BTl[(size_t)n * K + k] = __float2bfloat16(v - __bfloat162float(hi));
    }
}

// ---------------- prep: LN(kv_lat) + k_rope -> all-head K split ----------------
__global__ __launch_bounds__(128) void prep_kernel(
    const float* __restrict__ fc, const float* __restrict__ lnw, const float* __restrict__ lnb)
{
    const int tok = blockIdx.x;
    const int s   = tok & (Ss - 1);
    const int tid = threadIdx.x;

    const float* x = &g_kva[(size_t)tok * KVA_PAD];
    float local[4];
    float sum = 0.f;
    #pragma unroll
    for (int i = 0; i < 4; i++) { local[i] = x[tid + i * 128]; sum += local[i]; }
    __shared__ float red[4];
    __shared__ float kr[64];
    #pragma unroll
    for (int o = 16; o > 0; o >>= 1) sum += __shfl_xor_sync(0xffffffffu, sum, o);
    if ((tid & 31) == 0) red[tid >> 5] = sum;
    __syncthreads();
    const float mean = (red[0] + red[1] + red[2] + red[3]) * (1.f / 512.f);
    float vs = 0.f;
    #pragma unroll
    for (int i = 0; i < 4; i++) { float d = local[i] - mean; vs = fmaf(d, d, vs); }
    #pragma unroll
    for (int o = 16; o > 0; o >>= 1) vs += __shfl_xor_sync(0xffffffffu, vs, o);
    __syncthreads();
    if ((tid & 31) == 0) red[tid >> 5] = vs;
    if (tid < 32) {
        const float* fcs = &fc[(size_t)s * 64];
        float c  = fcs[tid * 2 + 0];
        float sn = fcs[tid * 2 + 1];
        float x0 = x[KVRANK + 2 * tid];
        float x1 = x[KVRANK + 2 * tid + 1];
        kr[2 * tid]     = x0 * c - x1 * sn;
        kr[2 * tid + 1] = x0 * sn + x1 * c;
    }
    __syncthreads();
    const float var  = (red[0] + red[1] + red[2] + red[3]) * (1.f / 512.f);
    const float rstd = rsqrtf(var + LN_EPS);
    #pragma unroll
    for (int i = 0; i < 4; i++) {
        int c = tid + i * 128;
        float v = (local[i] - mean) * rstd * lnw[c] + lnb[c];
        __nv_bfloat16 hi = __float2bfloat16(v);
        g_kvlat_h[(size_t)tok * KVRANK + c] = hi;
        g_kvlat_l[(size_t)tok * KVRANK + c] = __float2bfloat16(v - __bfloat162float(hi));
    }
    #pragma unroll
    for (int i = 0; i < 8; i++) {
        int e = tid + i * 128;
        int hh = e >> 6, k = e & 63;
        float v = kr[k];
        __nv_bfloat16 hi = __float2bfloat16(v);
        size_t dst = ((size_t)hh * NTOK + tok) * DQK + DNOPE + k;
        g_kh[dst] = hi;
        g_kl[dst] = __float2bfloat16(v - __bfloat162float(hi));
    }
}

// ---------------- flash attention v2: FQT=64, 128 threads, 2 CTAs/SM ----------------
// Q-hi resident in smem; Q-lo fragments resident in REGISTERS (staged via V area).
#define FQT 64
#define FKT 32
#define QKB 400
#define VB  272
#define OQH 0                      // Q hi: 64*400 = 25600
#define OKH 25600                  // K hi: 2 stages * 12800
#define OKL 51200                  // K lo: 2 stages * 12800
#define OVH 76800                  // V hi: 2 stages * 8704
#define OVL 94208                  // V lo: 2 stages * 8704
#define KSTG 12800
#define VSTG 8704
#define FSMEM 111616               // 2 CTAs/SM (223232 <= 228KB)

__global__ __launch_bounds__(128) void flash_mma(int b)
{
    const int qt   = (int)gridDim.x - 1 - (int)blockIdx.x;
    const int h    = blockIdx.y;
    const int tid  = threadIdx.x, w = tid >> 5, lane = tid & 31;   // w: 0..3
    extern __shared__ char fsm[];
    const uint32_t sb = smem_u32(fsm);
    const int q0 = qt * FQT;
    const size_t rowQ = (size_t)h * NTOK + (size_t)b * Ss + q0;
    const size_t rowK = (size_t)h * NTOK + (size_t)b * Ss;

    // load Q-hi -> OQH ; stage Q-lo -> OVH (V area, free until load_kv(0,0))
    #pragma unroll
    for (int i = 0; i < 12; i++) {
        int u = tid + i * 128;                 // 0..1535
        int row = u / 24, c = u % 24;
        const void* src = g_qh + (rowQ + row) * DQK + c * 8;
        uint32_t dst = sb + OQH + row * QKB + c * 16;
        asm volatile("cp.async.cg.shared.global [%0], [%1], 16;" :: "r"(dst), "l"(src));
    }
    #pragma unroll
    for (int i = 0; i < 12; i++) {
        int u = tid + i * 128;
        int row = u / 24, c = u % 24;
        const void* src = g_ql + (rowQ + row) * DQK + c * 8;
        uint32_t dst = sb + OVH + row * QKB + c * 16;
        asm volatile("cp.async.cg.shared.global [%0], [%1], 16;" :: "r"(dst), "l"(src));
    }
    asm volatile("cp.async.commit_group;" ::: "memory");
    asm volatile("cp.async.wait_group 0;" ::: "memory");
    __syncthreads();

    // ldsm Q-lo fragments into registers (warp w owns rows w*16..w*16+15)
    uint32_t ql[12][4];
    {
        const uint32_t qlo_off = sb + OVH + (w * 16 + (lane & 15)) * QKB + ((lane >> 4) << 4);
        #pragma unroll
        for (int ks = 0; ks < 12; ks++) ldsm4(ql[ks], qlo_off + ks * 32);
    }
    __syncthreads();     // V staging area free now

    auto load_kv = [&](int j, int st) {
        const int j0 = j * FKT;
        #pragma unroll
        for (int i = 0; i < 12; i++) {
            int u = tid + i * 128;             // 0..1535
            int sp = (u >= 768); int uu = u - sp * 768;
            int row = uu / 24, c = uu % 24;
            const void* src = (sp ? g_kl : g_kh) + (rowK + j0 + row) * DQK + c * 8;
            uint32_t dst = sb + (sp ? OKL : OKH) + st * KSTG + row * QKB + c * 16;
            asm volatile("cp.async.cg.shared.global [%0], [%1], 16;" :: "r"(dst), "l"(src));
        }
        #pragma unroll
        for (int i = 0; i < 8; i++) {
            int u = tid + i * 128;             // 0..1023
            int sp = (u >= 512); int uu = u - sp * 512;
            int row = uu >> 4, c = uu & 15;
            const void* src = (sp ? g_vl : g_vh) + (rowK + j0 + row) * DVv + c * 8;
            uint32_t dst = sb + (sp ? OVL : OVH) + st * VSTG + row * VB + c * 16;
            asm volatile("cp.async.cg.shared.global [%0], [%1], 16;" :: "r"(dst), "l"(src));
        }
        asm volatile("cp.async.commit_group;" ::: "memory");
    };
    load_kv(0, 0);

    float o[16][4];
    #pragma unroll
    for (int t = 0; t < 16; t++)
        #pragma unroll
        for (int e = 0; e < 4; e++) o[t][e] = 0.f;
    float mr[2] = {-1e30f, -1e30f}, lr[2] = {0.f, 0.f};

    const uint32_t q_off = sb + OQH + (w * 16 + (lane & 15)) * QKB + ((lane >> 4) << 4);
    const uint32_t kz = (lane & 15) * QKB + ((lane >> 4) << 4);
    const uint32_t vz = (lane & 15) * VB  + ((lane >> 4) << 4);
    const int nkt = q0 / FKT + 2;

    for (int j = 0; j < nkt; j++) {
        const int st = j & 1, j0 = j * FKT;
        if (j + 1 < nkt) {
            load_kv(j + 1, st ^ 1);
            asm volatile("cp.async.wait_group 1;" ::: "memory");
        } else {
            asm volatile("cp.async.wait_group 0;" ::: "memory");
        }
        __syncthreads();

        float sacc[4][4];
        #pragma unroll
        for (int t = 0; t < 4; t++)
            #pragma unroll
            for (int e = 0; e < 4; e++) sacc[t][e] = 0.f;

        #pragma unroll
        for (int ks = 0; ks < 12; ks++) {
            uint32_t qh4[4];
            ldsm4(qh4, q_off + ks * 32);
            #pragma unroll
            for (int nw = 0; nw < 2; nw++) {
                uint32_t kh4[4], kl4[4];
                uint32_t ka = sb + OKH + st * KSTG + nw * 16 * QKB + kz + ks * 32;
                ldsm4(kh4, ka);
                ldsm4(kl4, ka + (OKL - OKH));
                uint32_t bh0[2] = {kh4[0], kh4[2]}, bh1[2] = {kh4[1], kh4[3]};
                uint32_t bl0[2] = {kl4[0], kl4[2]}, bl1[2] = {kl4[1], kl4[3]};
                mma16816(sacc[nw * 2],     qh4,    bh0);
                mma16816(sacc[nw * 2 + 1], qh4,    bh1);
                mma16816(sacc[nw * 2],     qh4,    bl0);
                mma16816(sacc[nw * 2 + 1], qh4,    bl1);
                mma16816(sacc[nw * 2],     ql[ks], bh0);
                mma16816(sacc[nw * 2 + 1], ql[ks], bh1);
            }
        }

        if (j0 + FKT - 1 > q0) {
            #pragma unroll
            for (int t = 0; t < 4; t++)
                #pragma unroll
                for (int e = 0; e < 4; e++) {
                    int rowg = q0 + w * 16 + (lane >> 2) + (e >> 1) * 8;
                    int colg = j0 + t * 8 + (lane & 3) * 2 + (e & 1);
                    if (colg > rowg) sacc[t][e] = -1e30f;
                }
        }

        float alpha[2];
        #pragma unroll
        for (int rh = 0; rh < 2; rh++) {
            float mx = -1e30f;
            #pragma unroll
            for (int t = 0; t < 4; t++)
                mx = fmaxf(mx, fmaxf(sacc[t][rh * 2], sacc[t][rh * 2 + 1]));
            mx = fmaxf(mx, __shfl_xor_sync(0xffffffffu, mx, 1));
            mx = fmaxf(mx, __shfl_xor_sync(0xffffffffu, mx, 2));
            float mn = fmaxf(mr[rh], mx);
            alpha[rh] = ex2f(mr[rh] - mn);
            mr[rh] = mn;
            float rs = 0.f;
            #pragma unroll
            for (int t = 0; t < 4; t++) {
                float p0 = ex2f(sacc[t][rh * 2]     - mn);
                float p1 = ex2f(sacc[t][rh * 2 + 1] - mn);
                sacc[t][rh * 2] = p0; sacc[t][rh * 2 + 1] = p1;
                rs += p0 + p1;
            }
            rs += __shfl_xor_sync(0xffffffffu, rs, 1);
            rs += __shfl_xor_sync(0xffffffffu, rs, 2);
            lr[rh] = lr[rh] * alpha[rh] + rs;
        }
        #pragma unroll
        for (int t = 0; t < 16; t++) {
            o[t][0] *= alpha[0]; o[t][1] *= alpha[0];
            o[t][2] *= alpha[1]; o[t][3] *= alpha[1];
        }

        uint32_t ah[2][4], al[2][4];
        #pragma unroll
        for (int ks2 = 0; ks2 < 2; ks2++) {
            #pragma unroll
            for (int q = 0; q < 4; q++) {
                int t = ks2 * 2 + (q >> 1);
                int e = (q & 1) * 2;
                split2(sacc[t][e], sacc[t][e + 1], ah[ks2][q], al[ks2][q]);
            }
        }

        #pragma unroll
        for (int ks2 = 0; ks2 < 2; ks2++) {
            #pragma unroll
            for (int nw = 0; nw < 8; nw++) {
                uint32_t vh4[4], vl4[4];
                uint32_t va = sb + OVH + st * VSTG + ks2 * 16 * VB + vz + nw * 32;
                ldsm4t(vh4, va);
                ldsm4t(vl4, va + (OVL - OVH));
                uint32_t b0h[2] = {vh4[0], vh4[1]}, b1h[2] = {vh4[2], vh4[3]};
                uint32_t b0l[2] = {vl4[0], vl4[1]}, b1l[2] = {vl4[2], vl4[3]};
                mma16816(o[nw * 2],     ah[ks2], b0h);
                mma16816(o[nw * 2 + 1], ah[ks2], b1h);
                mma16816(o[nw * 2],     al[ks2], b0h);
                mma16816(o[nw * 2 + 1], al[ks2], b1h);
                mma16816(o[nw * 2],     ah[ks2], b0l);
                mma16816(o[nw * 2 + 1], ah[ks2], b1l);
            }
        }
        __syncthreads();
    }

    #pragma unroll
    for (int rh = 0; rh < 2; rh++) {
        float inv = 1.f / lr[rh];
        int row = q0 + w * 16 + (lane >> 2) + rh * 8;
        size_t gbase = ((size_t)b * Ss + row) * (NHh * DVv) + h * DVv;
        #pragma unroll
        for (int t = 0; t < 16; t++) {
            int d = t * 8 + (lane & 3) * 2;
            uint32_t hw, lw;
            split2(o[t][rh * 2] * inv, o[t][rh * 2 + 1] * inv, hw, lw);
            *(uint32_t*)&g_attn_h[gbase + d] = hw;
            *(uint32_t*)&g_attn_l[gbase + d] = lw;
        }
    }
}

// ---------------- launch: fork/join with per-batch flash->Wo pipelining ----------------
extern "C" void kernel_launch(void* const* d_in, const int* in_sizes, int n_in,
                              void* d_out, int out_size)
{
    const float* hs   = (const float*)d_in[0];
    const float* fc   = (const float*)d_in[1];
    const float* Wq   = (const float*)d_in[3];
    const float* Wkva = (const float*)d_in[4];
    const float* lnw  = (const float*)d_in[5];
    const float* lnb  = (const float*)d_in[6];
    const float* Wkvb = (const float*)d_in[7];
    const float* Wo   = (const float*)d_in[8];
    float* out = (float*)d_out;

    static bool init_done = false;
    static float *p_kva;
    static __nv_bfloat16 *p_hs_h, *p_hs_l, *p_WqT_h, *p_WqT_l, *p_WkvaT_h, *p_WkvaT_l,
                         *p_WkvbT_h, *p_WkvbT_l, *p_WoT_h, *p_WoT_l,
                         *p_kvlat_h, *p_kvlat_l, *p_attn_h, *p_attn_l;
    static cudaStream_t sA, sB;
    static cudaEvent_t evRoot, evQ, evKV, evA2, evB2;
    if (!init_done) {
        cudaGetSymbolAddress((void**)&p_kva,    g_kva);
        cudaGetSymbolAddress((void**)&p_hs_h,   g_hs_h);
        cudaGetSymbolAddress((void**)&p_hs_l,   g_hs_l);
        cudaGetSymbolAddress((void**)&p_WqT_h,  g_WqT_h);
        cudaGetSymbolAddress((void**)&p_WqT_l,  g_WqT_l);
        cudaGetSymbolAddress((void**)&p_WkvaT_h,g_WkvaT_h);
        cudaGetSymbolAddress((void**)&p_WkvaT_l,g_WkvaT_l);
        cudaGetSymbolAddress((void**)&p_WkvbT_h,g_WkvbT_h);
        cudaGetSymbolAddress((void**)&p_WkvbT_l,g_WkvbT_l);
        cudaGetSymbolAddress((void**)&p_WoT_h,  g_WoT_h);
        cudaGetSymbolAddress((void**)&p_WoT_l,  g_WoT_l);
        cudaGetSymbolAddress((void**)&p_kvlat_h,g_kvlat_h);
        cudaGetSymbolAddress((void**)&p_kvlat_l,g_kvlat_l);
        cudaGetSymbolAddress((void**)&p_attn_h, g_attn_h);
        cudaGetSymbolAddress((void**)&p_attn_l, g_attn_l);
        cudaFuncSetAttribute(mma_gemm<0>,
                             cudaFuncAttributeMaxDynamicSharedMemorySize, GS_SMEM);
        cudaFuncSetAttribute(mma_gemm<1>,
                             cudaFuncAttributeMaxDynamicSharedMemorySize, GS_SMEM);
        cudaFuncSetAttribute(mma_gemm<2>,
                             cudaFuncAttributeMaxDynamicSharedMemorySize, GS_SMEM);
        cudaFuncSetAttribute(flash_mma,
                             cudaFuncAttributeMaxDynamicSharedMemorySize, FSMEM);
        cudaStreamCreateWithFlags(&sA, cudaStreamNonBlocking);
        cudaStreamCreateWithFlags(&sB, cudaStreamNonBlocking);
        cudaEventCreateWithFlags(&evRoot, cudaEventDisableTiming);
        cudaEventCreateWithFlags(&evQ,    cudaEventDisableTiming);
        cudaEventCreateWithFlags(&evKV,   cudaEventDisableTiming);
        cudaEventCreateWithFlags(&evA2,   cudaEventDisableTiming);
        cudaEventCreateWithFlags(&evB2,   cudaEventDisableTiming);
        init_done = true;
    }

    // weight splits first: independent of hidden states
    split_T_kernel<<<dim3(3072/32, HIDc/32), dim3(32,8), 0, sA>>>(Wq, p_WqT_h, p_WqT_l, HIDc, 3072);
    split_T_kernel<<<dim3(KVA_PAD/32, HIDc/32), dim3(32,8), 0, sB>>>(Wkva, p_WkvaT_h, p_WkvaT_l, HIDc, 576);
    split_T_kernel<<<dim3(4096/32, KVRANK/32),  dim3(32,8), 0, sB>>>(Wkvb, p_WkvbT_h, p_WkvbT_l, KVRANK, 4096);

    // root: hidden-state split (needed by both GEMM chains)
    {
        int n4 = NTOK * HIDc / 4;
        split_rows_kernel<<<(n4 + 255) / 256, 256>>>(
            (const float4*)hs, (__nv_bfloat162*)p_hs_h, (__nv_bfloat162*)p_hs_l, n4);
    }
    cudaEventRecord(evRoot, 0);
    cudaStreamWaitEvent(sA, evRoot, 0);
    cudaStreamWaitEvent(sB, evRoot, 0);

    // ---- branch A: Wq chain ----
    mma_gemm<2><<<dim3(3072/128, NTOK/128), 256, GS_SMEM, sA>>>(
        p_hs_h, p_hs_l, p_WqT_h, p_WqT_l, nullptr, fc, NTOK, 3072, HIDc);
    cudaEventRecord(evQ, sA);                     // q ready (before Wo split)
    split_T_kernel<<<dim3(2048/32, HIDc/32), dim3(32,8), 0, sA>>>(Wo, p_WoT_h, p_WoT_l, HIDc, 2048);

    // ---- branch B: kv chain ----
    mma_gemm<0><<<dim3(KVA_PAD/128, NTOK/128), 256, GS_SMEM, sB>>>(
        p_hs_h, p_hs_l, p_WkvaT_h, p_WkvaT_l, p_kva, nullptr, NTOK, KVA_PAD, HIDc);
    prep_kernel<<<NTOK, 128, 0, sB>>>(fc, lnw, lnb);
    mma_gemm<1><<<dim3(4096/128, NTOK/128), 256, GS_SMEM, sB>>>(
        p_kvlat_h, p_kvlat_l, p_WkvbT_h, p_WkvbT_l, nullptr, nullptr, NTOK, 4096, KVRANK);
    cudaEventRecord(evKV, sB);                    // K/V ready

    // ---- cross waits: each stream runs flash for one batch then its Wo half ----
    cudaStreamWaitEvent(sA, evKV, 0);             // sA has q already (in-stream)
    cudaStreamWaitEvent(sB, evQ,  0);             // sB has K/V already (in-stream)

    // stream A: batch 0 attention + output rows [0, 2048)
    flash_mma<<<dim3(Ss/FQT, NHh), 128, FSMEM, sA>>>(0);
    mma_gemm<0><<<dim3(2048/128, 2048/128), 256, GS_SMEM, sA>>>(
        p_attn_h, p_attn_l, p_WoT_h, p_WoT_l, out, nullptr, 2048, 2048, HIDc);

    // stream B: batch 1 attention + output rows [2048, 4096)
    flash_mma<<<dim3(Ss/FQT, NHh), 128, FSMEM, sB>>>(1);
    mma_gemm<0><<<dim3(2048/128, 2048/128), 256, GS_SMEM, sB>>>(
        p_attn_h + (size_t)2048 * HIDc, p_attn_l + (size_t)2048 * HIDc,
        p_WoT_h, p_WoT_l, out + (size_t)2048 * HIDc, nullptr, 2048, 2048, HIDc);

    // ---- join back to origin stream ----
    cudaEventRecord(evA2, sA);
    cudaEventRecord(evB2, sB);
    cudaStreamWaitEvent(0, evA2, 0);
    cudaStreamWaitEvent(0, evB2, 0);
}